// round 1
// baseline (speedup 1.0000x reference)
#include <cuda_runtime.h>
#include <cuda_bf16.h>

// MPNN backbone: per layer l
//   A = x @ W1_l + msg_b_l        (gathered at dst)
//   B = x @ W2_l                  (gathered at src)
//   m_e = relu(A[dst_e] + B[src_e] + edge_attr_e @ W3_l)
//   agg  = scatter_add(m, dst)
//   x    = relu(x @ U1_l + agg @ U2_l + upd_b_l)
//
// msg_w: (L,144,64) rows 0..63 -> W1 (x_i = x[dst]), 64..127 -> W2 (x_j = x[src]),
//        128..143 -> W3 (edge_attr). upd_w: (L,128,64) rows 0..63 -> U1 (x), 64..127 -> U2 (agg).

#define MAX_N 50000
#define MAX_E 800000

__device__ float g_A  [MAX_N * 64];
__device__ float g_B  [MAX_N * 64];
__device__ float g_agg[MAX_N * 64];
__device__ float g_x1 [MAX_N * 64];
__device__ float g_x2 [MAX_N * 64];
__device__ int   g_is64;

// ---------------------------------------------------------------------------
// Detect whether edge_index is int64 or int32 on device.
// If data is int32 pairs read as int64, value = lo + hi*2^32 which is >= 2^32
// unless hi == 0 (p ~ 2e-5 per sample). 8 samples -> essentially certain.
// ---------------------------------------------------------------------------
__global__ void detect_idx_kernel(const long long* __restrict__ idx, int n_elem) {
    if (threadIdx.x == 0 && blockIdx.x == 0) {
        bool is64 = true;
        int cnt = n_elem < 8 ? n_elem : 8;
        for (int i = 0; i < cnt; ++i) {
            unsigned long long v = (unsigned long long)idx[i];
            if (v >= (unsigned long long)MAX_N) { is64 = false; break; }
        }
        g_is64 = is64 ? 1 : 0;
    }
}

// ---------------------------------------------------------------------------
// node_pre: A = x @ W1 + b, B = x @ W2, and zero agg for this block's nodes.
// Block = 256 threads = 8 warps, 64 nodes per block (warp handles 8 nodes).
// Weights staged in smem as float2 (cols 2c, 2c+1); x broadcast via shfl.
// ---------------------------------------------------------------------------
__global__ void node_pre_kernel(const float* __restrict__ x,
                                const float* __restrict__ mw,   // msg_w[l], 144x64
                                const float* __restrict__ mb,   // msg_b[l], 64
                                float* __restrict__ A,
                                float* __restrict__ B,
                                float* __restrict__ agg,
                                int n) {
    __shared__ float2 W1s[64][32];
    __shared__ float2 W2s[64][32];
    __shared__ float  bs[64];

    int tid = threadIdx.x;
    for (int i = tid; i < 2048; i += 256) {
        int k = i >> 5, c = i & 31;
        W1s[k][c] = make_float2(mw[k * 64 + 2 * c], mw[k * 64 + 2 * c + 1]);
        W2s[k][c] = make_float2(mw[(64 + k) * 64 + 2 * c], mw[(64 + k) * 64 + 2 * c + 1]);
    }
    if (tid < 64) bs[tid] = mb[tid];
    __syncthreads();

    int warp = tid >> 5, lane = tid & 31;
    int base = blockIdx.x * 64;

    // zero agg rows for this block's nodes (float4)
    if (base < n) {
        int nodes = min(64, n - base);
        float4* aggv = (float4*)(agg + (size_t)base * 64);
        int lim = nodes * 16;
        for (int i = tid; i < lim; i += 256) aggv[i] = make_float4(0.f, 0.f, 0.f, 0.f);
    }

    for (int it = 0; it < 8; ++it) {
        int node = base + it * 8 + warp;
        if (node >= n) break;
        float xv0 = x[node * 64 + lane];
        float xv1 = x[node * 64 + 32 + lane];
        float2 accA = make_float2(bs[2 * lane], bs[2 * lane + 1]);
        float2 accB = make_float2(0.f, 0.f);
#pragma unroll
        for (int k = 0; k < 32; ++k) {
            float xk = __shfl_sync(0xffffffffu, xv0, k);
            float2 w = W1s[k][lane]; accA.x += xk * w.x; accA.y += xk * w.y;
            w = W2s[k][lane];        accB.x += xk * w.x; accB.y += xk * w.y;
        }
#pragma unroll
        for (int k = 0; k < 32; ++k) {
            float xk = __shfl_sync(0xffffffffu, xv1, k);
            float2 w = W1s[32 + k][lane]; accA.x += xk * w.x; accA.y += xk * w.y;
            w = W2s[32 + k][lane];        accB.x += xk * w.x; accB.y += xk * w.y;
        }
        ((float2*)A)[node * 32 + lane] = accA;
        ((float2*)B)[node * 32 + lane] = accB;
    }
}

// ---------------------------------------------------------------------------
// edge: m = relu(A[dst] + B[src] + ea @ W3); atomic scatter-add into agg[dst].
// Warp per edge (grid-stride). Lane handles cols {2*lane, 2*lane+1}.
// ---------------------------------------------------------------------------
__global__ void edge_kernel(const float* __restrict__ A,
                            const float* __restrict__ B,
                            const void*  __restrict__ eidx,
                            const float* __restrict__ eattr,
                            const float* __restrict__ mw3,   // msg_w[l] + 128*64
                            float* __restrict__ agg,
                            int ne) {
    __shared__ float2 W3s[16][32];
    int tid = threadIdx.x;
    for (int i = tid; i < 512; i += blockDim.x) {
        int k = i >> 5, c = i & 31;
        W3s[k][c] = make_float2(mw3[k * 64 + 2 * c], mw3[k * 64 + 2 * c + 1]);
    }
    __syncthreads();

    int lane = tid & 31;
    int warpGlobal = (int)((blockIdx.x * blockDim.x + tid) >> 5);
    int nwarps = (int)((gridDim.x * blockDim.x) >> 5);
    const bool is64 = (g_is64 != 0);
    const long long* e64 = (const long long*)eidx;
    const int*       e32 = (const int*)eidx;

    for (int e = warpGlobal; e < ne; e += nwarps) {
        int src, dst;
        if (is64) { src = (int)e64[e]; dst = (int)e64[ne + e]; }
        else      { src = e32[e];      dst = e32[ne + e]; }

        float2 a = ((const float2*)A)[dst * 32 + lane];
        float2 b = ((const float2*)B)[src * 32 + lane];
        float ea = (lane < 16) ? eattr[(size_t)e * 16 + lane] : 0.f;
        float2 c = make_float2(0.f, 0.f);
#pragma unroll
        for (int k = 0; k < 16; ++k) {
            float ev = __shfl_sync(0xffffffffu, ea, k);
            float2 w = W3s[k][lane];
            c.x += ev * w.x; c.y += ev * w.y;
        }
        float mx = fmaxf(a.x + b.x + c.x, 0.f);
        float my = fmaxf(a.y + b.y + c.y, 0.f);
        float* p = agg + (size_t)dst * 64 + 2 * lane;
        atomicAdd(p, mx);
        atomicAdd(p + 1, my);
    }
}

// ---------------------------------------------------------------------------
// update: x_out = relu(x @ U1 + agg @ U2 + ub). Same scheme as node_pre.
// ---------------------------------------------------------------------------
__global__ void update_kernel(const float* __restrict__ x,
                              const float* __restrict__ agg,
                              const float* __restrict__ uw,   // upd_w[l], 128x64
                              const float* __restrict__ ub,   // upd_b[l], 64
                              float* __restrict__ xout,
                              int n) {
    __shared__ float2 U1s[64][32];
    __shared__ float2 U2s[64][32];
    __shared__ float  bs[64];

    int tid = threadIdx.x;
    for (int i = tid; i < 2048; i += 256) {
        int k = i >> 5, c = i & 31;
        U1s[k][c] = make_float2(uw[k * 64 + 2 * c], uw[k * 64 + 2 * c + 1]);
        U2s[k][c] = make_float2(uw[(64 + k) * 64 + 2 * c], uw[(64 + k) * 64 + 2 * c + 1]);
    }
    if (tid < 64) bs[tid] = ub[tid];
    __syncthreads();

    int warp = tid >> 5, lane = tid & 31;
    int base = blockIdx.x * 64;

    for (int it = 0; it < 8; ++it) {
        int node = base + it * 8 + warp;
        if (node >= n) break;
        float xv0 = x[node * 64 + lane];
        float xv1 = x[node * 64 + 32 + lane];
        float gv0 = agg[node * 64 + lane];
        float gv1 = agg[node * 64 + 32 + lane];
        float2 acc = make_float2(bs[2 * lane], bs[2 * lane + 1]);
#pragma unroll
        for (int k = 0; k < 32; ++k) {
            float xk = __shfl_sync(0xffffffffu, xv0, k);
            float2 w = U1s[k][lane]; acc.x += xk * w.x; acc.y += xk * w.y;
            float gk = __shfl_sync(0xffffffffu, gv0, k);
            w = U2s[k][lane];        acc.x += gk * w.x; acc.y += gk * w.y;
        }
#pragma unroll
        for (int k = 0; k < 32; ++k) {
            float xk = __shfl_sync(0xffffffffu, xv1, k);
            float2 w = U1s[32 + k][lane]; acc.x += xk * w.x; acc.y += xk * w.y;
            float gk = __shfl_sync(0xffffffffu, gv1, k);
            w = U2s[32 + k][lane];        acc.x += gk * w.x; acc.y += gk * w.y;
        }
        acc.x = fmaxf(acc.x, 0.f);
        acc.y = fmaxf(acc.y, 0.f);
        ((float2*)xout)[node * 32 + lane] = acc;
    }
}

extern "C" void kernel_launch(void* const* d_in, const int* in_sizes, int n_in,
                              void* d_out, int out_size) {
    const float* x_in   = (const float*)d_in[0];
    const void*  eidx   = d_in[1];
    const float* eattr  = (const float*)d_in[2];
    const float* msg_w  = (const float*)d_in[3];
    const float* msg_b  = (const float*)d_in[4];
    const float* upd_w  = (const float*)d_in[5];
    const float* upd_b  = (const float*)d_in[6];
    float* out = (float*)d_out;

    int n  = in_sizes[0] / 64;     // nodes
    int ne = in_sizes[2] / 16;     // edges
    if (n > MAX_N)  n  = MAX_N;
    if (ne > MAX_E) ne = MAX_E;

    float *dA, *dB, *dAgg, *dX1, *dX2;
    cudaGetSymbolAddress((void**)&dA,   g_A);
    cudaGetSymbolAddress((void**)&dB,   g_B);
    cudaGetSymbolAddress((void**)&dAgg, g_agg);
    cudaGetSymbolAddress((void**)&dX1,  g_x1);
    cudaGetSymbolAddress((void**)&dX2,  g_x2);

    detect_idx_kernel<<<1, 32>>>((const long long*)eidx, 2 * ne);

    int node_blocks = (n + 63) / 64;
    int edge_blocks = 1184;   // ~8 blocks/SM on 148 SMs, grid-stride

    const float* x_cur = x_in;
    const int L = 3;
    for (int l = 0; l < L; ++l) {
        const float* mw = msg_w + (size_t)l * 144 * 64;
        const float* mb = msg_b + (size_t)l * 64;
        const float* uw = upd_w + (size_t)l * 128 * 64;
        const float* ub = upd_b + (size_t)l * 64;
        float* x_next = (l == L - 1) ? out : (l == 0 ? dX1 : dX2);

        node_pre_kernel<<<node_blocks, 256>>>(x_cur, mw, mb, dA, dB, dAgg, n);
        edge_kernel<<<edge_blocks, 256>>>(dA, dB, eidx, eattr, mw + 128 * 64, dAgg, ne);
        update_kernel<<<node_blocks, 256>>>(x_cur, dAgg, uw, ub, x_next, n);

        x_cur = x_next;
    }
}

// round 8
// speedup vs baseline: 1.3661x; 1.3661x over previous
#include <cuda_runtime.h>
#include <cuda_bf16.h>

// MPNN backbone, CSR aggregation + register-blocked GEMMs.
// Per layer l:
//   A = x @ W1_l + msg_b_l   (indexed at dst)
//   B = x @ W2_l             (indexed at src)
//   agg[v] = sum_{e: dst(e)=v} relu(A[v] + B[src(e)] + edge_attr[e] @ W3_l)
//   x = relu(x @ U1_l + agg @ U2_l + upd_b_l)
//
// edge_index is layer-invariant -> build dst-sorted CSR once per launch;
// aggregate with one warp per dst node, zero atomics in the hot path.

#define MAX_N 50000
#define MAX_E 800000

__device__ float g_A  [MAX_N * 64];
__device__ float g_B  [MAX_N * 64];
__device__ float g_agg[MAX_N * 64];
__device__ float g_x1 [MAX_N * 64];
__device__ float g_x2 [MAX_N * 64];

__device__ int g_deg   [MAX_N + 1];
__device__ int g_rowptr[MAX_N + 1];
__device__ int g_cursor[MAX_N];
__device__ int g_essrc [MAX_E];
__device__ int g_eseid [MAX_E];
__device__ int g_srcA  [MAX_E];
__device__ int g_is64;

// ---------------------------------------------------------------------------
// Detect int64 vs int32 edge_index (JAX without x64 emits int32 silently).
// int32 pairs misread as int64 give values >= 2^32 with overwhelming prob.
// ---------------------------------------------------------------------------
__global__ void detect_idx_kernel(const long long* __restrict__ idx, int n_elem) {
    if (threadIdx.x == 0 && blockIdx.x == 0) {
        bool is64 = true;
        int cnt = n_elem < 8 ? n_elem : 8;
        for (int i = 0; i < cnt; ++i) {
            unsigned long long v = (unsigned long long)idx[i];
            if (v >= (unsigned long long)MAX_N) { is64 = false; break; }
        }
        g_is64 = is64 ? 1 : 0;
    }
}

__global__ void zero_deg_kernel(int* __restrict__ deg, int n1) {
    int i = blockIdx.x * blockDim.x + threadIdx.x;
    if (i < n1) deg[i] = 0;
}

// extract src -> srcA, histogram dst -> deg
__global__ void extract_hist_kernel(const void* __restrict__ eidx,
                                    int* __restrict__ srcA,
                                    int* __restrict__ deg,
                                    int ne) {
    int stride = gridDim.x * blockDim.x;
    const bool is64 = (g_is64 != 0);
    const long long* e64 = (const long long*)eidx;
    const int*       e32 = (const int*)eidx;
    for (int e = blockIdx.x * blockDim.x + threadIdx.x; e < ne; e += stride) {
        int src, dst;
        if (is64) { src = (int)e64[e]; dst = (int)e64[ne + e]; }
        else      { src = e32[e];      dst = e32[ne + e]; }
        srcA[e] = src;
        atomicAdd(&deg[dst], 1);
    }
}

// single-block exclusive scan over deg[0..n) -> rowptr, cursor; rowptr[n] = E
__global__ void scan_kernel(const int* __restrict__ deg,
                            int* __restrict__ rowptr,
                            int* __restrict__ cursor,
                            int n) {
    __shared__ int ssum[1024];
    int t = threadIdx.x;
    int chunk = (n + 1023) >> 10;
    int start = t * chunk;
    int end = start + chunk; if (end > n) end = n;
    int s = 0;
    for (int i = start; i < end; ++i) s += deg[i];
    ssum[t] = s;
    __syncthreads();
    for (int off = 1; off < 1024; off <<= 1) {
        int v = (t >= off) ? ssum[t - off] : 0;
        __syncthreads();
        ssum[t] += v;
        __syncthreads();
    }
    int base = (t == 0) ? 0 : ssum[t - 1];
    for (int i = start; i < end; ++i) {
        rowptr[i] = base;
        cursor[i] = base;
        base += deg[i];
    }
    if (t == 1023) rowptr[n] = ssum[1023];
}

// scatter edges into CSR slots (in-segment order nondeterministic; only
// permutes fp add order, same property as the atomic formulation)
__global__ void scatter_kernel(const void* __restrict__ eidx,
                               const int* __restrict__ srcA,
                               int* __restrict__ cursor,
                               int* __restrict__ es_src,
                               int* __restrict__ es_eid,
                               int ne) {
    int stride = gridDim.x * blockDim.x;
    const bool is64 = (g_is64 != 0);
    const long long* e64 = (const long long*)eidx;
    const int*       e32 = (const int*)eidx;
    for (int e = blockIdx.x * blockDim.x + threadIdx.x; e < ne; e += stride) {
        int dst = is64 ? (int)e64[ne + e] : e32[ne + e];
        int slot = atomicAdd(&cursor[dst], 1);
        es_src[slot] = srcA[e];
        es_eid[slot] = e;
    }
}

// ---------------------------------------------------------------------------
// node_pre: A = x @ W1 + b, B = x @ W2.
// 8 warps/block; each warp computes 8 nodes with register blocking so every
// weight float2 LDS is amortized over 8 nodes (32 FFMA / 2 LDS.64 per k).
// ---------------------------------------------------------------------------
__global__ void node_pre_kernel(const float* __restrict__ x,
                                const float* __restrict__ mw,   // 144x64
                                const float* __restrict__ mb,   // 64
                                float* __restrict__ A,
                                float* __restrict__ B,
                                int n) {
    __shared__ float2 W1s[64][32];
    __shared__ float2 W2s[64][32];
    __shared__ float  bs[64];

    int tid = threadIdx.x;
    for (int i = tid; i < 2048; i += 256) {
        int k = i >> 5, c = i & 31;
        W1s[k][c] = make_float2(mw[k * 64 + 2 * c], mw[k * 64 + 2 * c + 1]);
        W2s[k][c] = make_float2(mw[(64 + k) * 64 + 2 * c], mw[(64 + k) * 64 + 2 * c + 1]);
    }
    if (tid < 64) bs[tid] = mb[tid];
    __syncthreads();

    int warp = tid >> 5, lane = tid & 31;
    int node0 = blockIdx.x * 64 + warp * 8;
    if (node0 >= n) return;

    float xv0[8], xv1[8];
    float2 accA[8], accB[8];
#pragma unroll
    for (int i = 0; i < 8; ++i) {
        int nd = node0 + i;
        bool v = nd < n;
        xv0[i] = v ? x[nd * 64 + lane] : 0.f;
        xv1[i] = v ? x[nd * 64 + 32 + lane] : 0.f;
        accA[i] = make_float2(bs[2 * lane], bs[2 * lane + 1]);
        accB[i] = make_float2(0.f, 0.f);
    }

#pragma unroll 8
    for (int k = 0; k < 32; ++k) {
        float2 w1 = W1s[k][lane];
        float2 w2 = W2s[k][lane];
#pragma unroll
        for (int i = 0; i < 8; ++i) {
            float xk = __shfl_sync(0xffffffffu, xv0[i], k);
            accA[i].x += xk * w1.x; accA[i].y += xk * w1.y;
            accB[i].x += xk * w2.x; accB[i].y += xk * w2.y;
        }
    }
#pragma unroll 8
    for (int k = 0; k < 32; ++k) {
        float2 w1 = W1s[32 + k][lane];
        float2 w2 = W2s[32 + k][lane];
#pragma unroll
        for (int i = 0; i < 8; ++i) {
            float xk = __shfl_sync(0xffffffffu, xv1[i], k);
            accA[i].x += xk * w1.x; accA[i].y += xk * w1.y;
            accB[i].x += xk * w2.x; accB[i].y += xk * w2.y;
        }
    }

#pragma unroll
    for (int i = 0; i < 8; ++i) {
        int nd = node0 + i;
        if (nd < n) {
            ((float2*)A)[nd * 32 + lane] = accA[i];
            ((float2*)B)[nd * 32 + lane] = accB[i];
        }
    }
}

// ---------------------------------------------------------------------------
// agg: one warp per dst node, register accumulation, no atomics.
// B gathers hit L2 (B = 12.8 MB << 126 MB L2).
// ---------------------------------------------------------------------------
__global__ void agg_kernel(const float* __restrict__ A,
                           const float* __restrict__ B,
                           const float* __restrict__ eattr,
                           const int* __restrict__ rowptr,
                           const int* __restrict__ es_src,
                           const int* __restrict__ es_eid,
                           const float* __restrict__ mw3,   // 16x64
                           float* __restrict__ agg,
                           int n) {
    __shared__ float2 W3s[16][32];
    int tid = threadIdx.x;
    for (int i = tid; i < 512; i += blockDim.x) {
        int k = i >> 5, c = i & 31;
        W3s[k][c] = make_float2(mw3[k * 64 + 2 * c], mw3[k * 64 + 2 * c + 1]);
    }
    __syncthreads();

    int warp = tid >> 5, lane = tid & 31;
    int node = blockIdx.x * 8 + warp;
    if (node >= n) return;

    float2 a = ((const float2*)A)[node * 32 + lane];
    float2 acc = make_float2(0.f, 0.f);
    int s   = rowptr[node];
    int end = rowptr[node + 1];

    if (s < end) {
        int src = es_src[s];
        int eid = es_eid[s];
        while (s < end) {
            float2 b = ((const float2*)B)[src * 32 + lane];
            float ea = (lane < 16) ? eattr[(size_t)eid * 16 + lane] : 0.f;
            ++s;
            if (s < end) { src = es_src[s]; eid = es_eid[s]; }  // prefetch next
            float2 c = make_float2(0.f, 0.f);
#pragma unroll
            for (int k = 0; k < 16; ++k) {
                float ev = __shfl_sync(0xffffffffu, ea, k);
                float2 w = W3s[k][lane];
                c.x += ev * w.x; c.y += ev * w.y;
            }
            acc.x += fmaxf(a.x + b.x + c.x, 0.f);
            acc.y += fmaxf(a.y + b.y + c.y, 0.f);
        }
    }
    ((float2*)agg)[node * 32 + lane] = acc;
}

// ---------------------------------------------------------------------------
// update: x_out = relu([x, agg] @ U + ub), U = 128x64 in smem.
// 8-node register blocking.
// ---------------------------------------------------------------------------
__global__ void update_kernel(const float* __restrict__ x,
                              const float* __restrict__ agg,
                              const float* __restrict__ uw,   // 128x64
                              const float* __restrict__ ub,   // 64
                              float* __restrict__ xout,
                              int n) {
    __shared__ float2 Us[128][32];
    __shared__ float  bs[64];

    int tid = threadIdx.x;
    for (int i = tid; i < 4096; i += 256) {
        int k = i >> 5, c = i & 31;
        Us[k][c] = make_float2(uw[k * 64 + 2 * c], uw[k * 64 + 2 * c + 1]);
    }
    if (tid < 64) bs[tid] = ub[tid];
    __syncthreads();

    int warp = tid >> 5, lane = tid & 31;
    int node0 = blockIdx.x * 64 + warp * 8;
    if (node0 >= n) return;

    float xv0[8], xv1[8], gv0[8], gv1[8];
    float2 acc[8];
#pragma unroll
    for (int i = 0; i < 8; ++i) {
        int nd = node0 + i;
        bool v = nd < n;
        xv0[i] = v ? x[nd * 64 + lane] : 0.f;
        xv1[i] = v ? x[nd * 64 + 32 + lane] : 0.f;
        gv0[i] = v ? agg[nd * 64 + lane] : 0.f;
        gv1[i] = v ? agg[nd * 64 + 32 + lane] : 0.f;
        acc[i] = make_float2(bs[2 * lane], bs[2 * lane + 1]);
    }

#pragma unroll 8
    for (int k = 0; k < 32; ++k) {
        float2 w = Us[k][lane];
#pragma unroll
        for (int i = 0; i < 8; ++i) {
            float vk = __shfl_sync(0xffffffffu, xv0[i], k);
            acc[i].x += vk * w.x; acc[i].y += vk * w.y;
        }
    }
#pragma unroll 8
    for (int k = 0; k < 32; ++k) {
        float2 w = Us[32 + k][lane];
#pragma unroll
        for (int i = 0; i < 8; ++i) {
            float vk = __shfl_sync(0xffffffffu, xv1[i], k);
            acc[i].x += vk * w.x; acc[i].y += vk * w.y;
        }
    }
#pragma unroll 8
    for (int k = 0; k < 32; ++k) {
        float2 w = Us[64 + k][lane];
#pragma unroll
        for (int i = 0; i < 8; ++i) {
            float vk = __shfl_sync(0xffffffffu, gv0[i], k);
            acc[i].x += vk * w.x; acc[i].y += vk * w.y;
        }
    }
#pragma unroll 8
    for (int k = 0; k < 32; ++k) {
        float2 w = Us[96 + k][lane];
#pragma unroll
        for (int i = 0; i < 8; ++i) {
            float vk = __shfl_sync(0xffffffffu, gv1[i], k);
            acc[i].x += vk * w.x; acc[i].y += vk * w.y;
        }
    }

#pragma unroll
    for (int i = 0; i < 8; ++i) {
        int nd = node0 + i;
        if (nd < n) {
            acc[i].x = fmaxf(acc[i].x, 0.f);
            acc[i].y = fmaxf(acc[i].y, 0.f);
            ((float2*)xout)[nd * 32 + lane] = acc[i];
        }
    }
}

extern "C" void kernel_launch(void* const* d_in, const int* in_sizes, int n_in,
                              void* d_out, int out_size) {
    const float* x_in   = (const float*)d_in[0];
    const void*  eidx   = d_in[1];
    const float* eattr  = (const float*)d_in[2];
    const float* msg_w  = (const float*)d_in[3];
    const float* msg_b  = (const float*)d_in[4];
    const float* upd_w  = (const float*)d_in[5];
    const float* upd_b  = (const float*)d_in[6];
    float* out = (float*)d_out;

    int n  = in_sizes[0] / 64;     // nodes
    int ne = in_sizes[2] / 16;     // edges
    if (n > MAX_N)  n  = MAX_N;
    if (ne > MAX_E) ne = MAX_E;

    float *dA, *dB, *dAgg, *dX1, *dX2;
    int *dDeg, *dRow, *dCur, *dEsSrc, *dEsEid, *dSrcA;
    cudaGetSymbolAddress((void**)&dA,     g_A);
    cudaGetSymbolAddress((void**)&dB,     g_B);
    cudaGetSymbolAddress((void**)&dAgg,   g_agg);
    cudaGetSymbolAddress((void**)&dX1,    g_x1);
    cudaGetSymbolAddress((void**)&dX2,    g_x2);
    cudaGetSymbolAddress((void**)&dDeg,   g_deg);
    cudaGetSymbolAddress((void**)&dRow,   g_rowptr);
    cudaGetSymbolAddress((void**)&dCur,   g_cursor);
    cudaGetSymbolAddress((void**)&dEsSrc, g_essrc);
    cudaGetSymbolAddress((void**)&dEsEid, g_eseid);
    cudaGetSymbolAddress((void**)&dSrcA,  g_srcA);

    // ---- once per launch: CSR build (edge_index is layer-invariant) ----
    detect_idx_kernel<<<1, 32>>>((const long long*)eidx, 2 * ne);
    zero_deg_kernel<<<(n + 256) / 256, 256>>>(dDeg, n + 1);
    int eb = (ne + 255) / 256;
    if (eb > 3072) eb = 3072;
    extract_hist_kernel<<<eb, 256>>>(eidx, dSrcA, dDeg, ne);
    scan_kernel<<<1, 1024>>>(dDeg, dRow, dCur, n);
    scatter_kernel<<<eb, 256>>>(eidx, dSrcA, dCur, dEsSrc, dEsEid, ne);

    int node_blocks = (n + 63) / 64;
    int agg_blocks  = (n + 7) / 8;

    const float* x_cur = x_in;
    const int L = 3;
    for (int l = 0; l < L; ++l) {
        const float* mw = msg_w + (size_t)l * 144 * 64;
        const float* mb = msg_b + (size_t)l * 64;
        const float* uw = upd_w + (size_t)l * 128 * 64;
        const float* ub = upd_b + (size_t)l * 64;
        float* x_next = (l == L - 1) ? out : (l == 0 ? dX1 : dX2);

        node_pre_kernel<<<node_blocks, 256>>>(x_cur, mw, mb, dA, dB, n);
        agg_kernel<<<agg_blocks, 256>>>(dA, dB, eattr, dRow, dEsSrc, dEsEid,
                                        mw + 128 * 64, dAgg, n);
        update_kernel<<<node_blocks, 256>>>(x_cur, dAgg, uw, ub, x_next, n);

        x_cur = x_next;
    }
}

// round 9
// speedup vs baseline: 1.4963x; 1.0953x over previous
#include <cuda_runtime.h>
#include <cuda_bf16.h>

// MPNN backbone, CSR aggregation + register-blocked GEMMs.
// Per layer l:
//   A = x @ W1_l + msg_b_l   (indexed at dst)
//   B = x @ W2_l             (indexed at src)
//   agg[v] = sum_{e: dst(e)=v} relu(A[v] + B[src(e)] + edge_attr[e] @ W3_l)
//   x = relu(x @ U1_l + agg @ U2_l + upd_b_l)
//
// edge_index is layer-invariant -> build dst-sorted CSR once per launch;
// aggregate with one warp per dst node, zero atomics in the hot path.
// R8 changes: multi-block scan (was 71.6us single-block), int2-packed CSR payload.

#define MAX_N 50000
#define MAX_E 800000
#define SCAN_CHUNK 256
#define MAX_BLOCKS ((MAX_N + SCAN_CHUNK - 1) / SCAN_CHUNK + 1)

__device__ float g_A  [MAX_N * 64];
__device__ float g_B  [MAX_N * 64];
__device__ float g_agg[MAX_N * 64];
__device__ float g_x1 [MAX_N * 64];
__device__ float g_x2 [MAX_N * 64];

__device__ int  g_deg   [MAX_N + 1];
__device__ int  g_rowptr[MAX_N + 1];
__device__ int  g_cursor[MAX_N];
__device__ int2 g_espack[MAX_E];     // (src, eid) per CSR slot
__device__ int  g_srcA  [MAX_E];
__device__ int  g_bsums [MAX_BLOCKS];
__device__ int  g_is64;

// ---------------------------------------------------------------------------
// Detect int64 vs int32 edge_index (JAX without x64 emits int32 silently).
// ---------------------------------------------------------------------------
__global__ void detect_idx_kernel(const long long* __restrict__ idx, int n_elem) {
    if (threadIdx.x == 0 && blockIdx.x == 0) {
        bool is64 = true;
        int cnt = n_elem < 8 ? n_elem : 8;
        for (int i = 0; i < cnt; ++i) {
            unsigned long long v = (unsigned long long)idx[i];
            if (v >= (unsigned long long)MAX_N) { is64 = false; break; }
        }
        g_is64 = is64 ? 1 : 0;
    }
}

__global__ void zero_deg_kernel(int* __restrict__ deg, int n1) {
    int i = blockIdx.x * blockDim.x + threadIdx.x;
    if (i < n1) deg[i] = 0;
}

// extract src -> srcA, histogram dst -> deg
__global__ void extract_hist_kernel(const void* __restrict__ eidx,
                                    int* __restrict__ srcA,
                                    int* __restrict__ deg,
                                    int ne) {
    int stride = gridDim.x * blockDim.x;
    const bool is64 = (g_is64 != 0);
    const long long* e64 = (const long long*)eidx;
    const int*       e32 = (const int*)eidx;
    for (int e = blockIdx.x * blockDim.x + threadIdx.x; e < ne; e += stride) {
        int src, dst;
        if (is64) { src = (int)e64[e]; dst = (int)e64[ne + e]; }
        else      { src = e32[e];      dst = e32[ne + e]; }
        srcA[e] = src;
        atomicAdd(&deg[dst], 1);
    }
}

// ---------------------------------------------------------------------------
// Multi-block exclusive scan: (1) per-block sum, (2) 1-block scan of block
// sums, (3) per-block local scan + offset -> rowptr/cursor; rowptr[n] = E.
// ---------------------------------------------------------------------------
__global__ void scan_reduce_kernel(const int* __restrict__ deg,
                                   int* __restrict__ bsums, int n) {
    __shared__ int sd[SCAN_CHUNK];
    int i = blockIdx.x * SCAN_CHUNK + threadIdx.x;
    int v = (i < n) ? deg[i] : 0;
    sd[threadIdx.x] = v;
    __syncthreads();
    for (int off = SCAN_CHUNK / 2; off > 0; off >>= 1) {
        if (threadIdx.x < off) sd[threadIdx.x] += sd[threadIdx.x + off];
        __syncthreads();
    }
    if (threadIdx.x == 0) bsums[blockIdx.x] = sd[0];
}

__global__ void scan_bsums_kernel(int* __restrict__ bsums,
                                  int* __restrict__ rowptr,
                                  int nb, int n) {
    __shared__ int ss[1024];
    int t = threadIdx.x;
    int v = (t < nb) ? bsums[t] : 0;
    ss[t] = v;
    __syncthreads();
    for (int off = 1; off < 1024; off <<= 1) {
        int u = (t >= off) ? ss[t - off] : 0;
        __syncthreads();
        ss[t] += u;
        __syncthreads();
    }
    if (t < nb) bsums[t] = ss[t] - v;      // exclusive offset
    if (t == 1023) rowptr[n] = ss[1023];   // total = E
}

__global__ void scan_output_kernel(const int* __restrict__ deg,
                                   const int* __restrict__ bsums,
                                   int* __restrict__ rowptr,
                                   int* __restrict__ cursor, int n) {
    __shared__ int sd[SCAN_CHUNK];
    int i = blockIdx.x * SCAN_CHUNK + threadIdx.x;
    int v = (i < n) ? deg[i] : 0;
    sd[threadIdx.x] = v;
    __syncthreads();
    // inclusive Hillis-Steele in smem
    for (int off = 1; off < SCAN_CHUNK; off <<= 1) {
        int u = (threadIdx.x >= off) ? sd[threadIdx.x - off] : 0;
        __syncthreads();
        sd[threadIdx.x] += u;
        __syncthreads();
    }
    if (i < n) {
        int excl = bsums[blockIdx.x] + sd[threadIdx.x] - v;
        rowptr[i] = excl;
        cursor[i] = excl;
    }
}

// scatter edges into CSR slots, payload packed as int2(src, eid)
__global__ void scatter_kernel(const void* __restrict__ eidx,
                               const int* __restrict__ srcA,
                               int* __restrict__ cursor,
                               int2* __restrict__ espack,
                               int ne) {
    int stride = gridDim.x * blockDim.x;
    const bool is64 = (g_is64 != 0);
    const long long* e64 = (const long long*)eidx;
    const int*       e32 = (const int*)eidx;
    for (int e = blockIdx.x * blockDim.x + threadIdx.x; e < ne; e += stride) {
        int dst = is64 ? (int)e64[ne + e] : e32[ne + e];
        int slot = atomicAdd(&cursor[dst], 1);
        espack[slot] = make_int2(srcA[e], e);
    }
}

// ---------------------------------------------------------------------------
// node_pre: A = x @ W1 + b, B = x @ W2.
// 8 warps/block; each warp computes 8 nodes with register blocking so every
// weight float2 LDS is amortized over 8 nodes (32 FFMA / 2 LDS.64 per k).
// ---------------------------------------------------------------------------
__global__ void node_pre_kernel(const float* __restrict__ x,
                                const float* __restrict__ mw,   // 144x64
                                const float* __restrict__ mb,   // 64
                                float* __restrict__ A,
                                float* __restrict__ B,
                                int n) {
    __shared__ float2 W1s[64][32];
    __shared__ float2 W2s[64][32];
    __shared__ float  bs[64];

    int tid = threadIdx.x;
    for (int i = tid; i < 2048; i += 256) {
        int k = i >> 5, c = i & 31;
        W1s[k][c] = make_float2(mw[k * 64 + 2 * c], mw[k * 64 + 2 * c + 1]);
        W2s[k][c] = make_float2(mw[(64 + k) * 64 + 2 * c], mw[(64 + k) * 64 + 2 * c + 1]);
    }
    if (tid < 64) bs[tid] = mb[tid];
    __syncthreads();

    int warp = tid >> 5, lane = tid & 31;
    int node0 = blockIdx.x * 64 + warp * 8;
    if (node0 >= n) return;

    float xv0[8], xv1[8];
    float2 accA[8], accB[8];
#pragma unroll
    for (int i = 0; i < 8; ++i) {
        int nd = node0 + i;
        bool v = nd < n;
        xv0[i] = v ? x[nd * 64 + lane] : 0.f;
        xv1[i] = v ? x[nd * 64 + 32 + lane] : 0.f;
        accA[i] = make_float2(bs[2 * lane], bs[2 * lane + 1]);
        accB[i] = make_float2(0.f, 0.f);
    }

#pragma unroll 8
    for (int k = 0; k < 32; ++k) {
        float2 w1 = W1s[k][lane];
        float2 w2 = W2s[k][lane];
#pragma unroll
        for (int i = 0; i < 8; ++i) {
            float xk = __shfl_sync(0xffffffffu, xv0[i], k);
            accA[i].x += xk * w1.x; accA[i].y += xk * w1.y;
            accB[i].x += xk * w2.x; accB[i].y += xk * w2.y;
        }
    }
#pragma unroll 8
    for (int k = 0; k < 32; ++k) {
        float2 w1 = W1s[32 + k][lane];
        float2 w2 = W2s[32 + k][lane];
#pragma unroll
        for (int i = 0; i < 8; ++i) {
            float xk = __shfl_sync(0xffffffffu, xv1[i], k);
            accA[i].x += xk * w1.x; accA[i].y += xk * w1.y;
            accB[i].x += xk * w2.x; accB[i].y += xk * w2.y;
        }
    }

#pragma unroll
    for (int i = 0; i < 8; ++i) {
        int nd = node0 + i;
        if (nd < n) {
            ((float2*)A)[nd * 32 + lane] = accA[i];
            ((float2*)B)[nd * 32 + lane] = accB[i];
        }
    }
}

// ---------------------------------------------------------------------------
// agg: one warp per dst node, register accumulation, no atomics.
// CSR payload is int2(src, eid): single LDG.64 per edge.
// ---------------------------------------------------------------------------
__global__ void agg_kernel(const float* __restrict__ A,
                           const float* __restrict__ B,
                           const float* __restrict__ eattr,
                           const int* __restrict__ rowptr,
                           const int2* __restrict__ espack,
                           const float* __restrict__ mw3,   // 16x64
                           float* __restrict__ agg,
                           int n) {
    __shared__ float2 W3s[16][32];
    int tid = threadIdx.x;
    for (int i = tid; i < 512; i += blockDim.x) {
        int k = i >> 5, c = i & 31;
        W3s[k][c] = make_float2(mw3[k * 64 + 2 * c], mw3[k * 64 + 2 * c + 1]);
    }
    __syncthreads();

    int warp = tid >> 5, lane = tid & 31;
    int node = blockIdx.x * 8 + warp;
    if (node >= n) return;

    float2 a = ((const float2*)A)[node * 32 + lane];
    float2 acc = make_float2(0.f, 0.f);
    int s   = rowptr[node];
    int end = rowptr[node + 1];

    if (s < end) {
        int2 se = espack[s];
        while (s < end) {
            float2 b = ((const float2*)B)[se.x * 32 + lane];
            float ea = (lane < 16) ? eattr[(size_t)se.y * 16 + lane] : 0.f;
            ++s;
            if (s < end) se = espack[s];   // prefetch next
            float2 c = make_float2(0.f, 0.f);
#pragma unroll
            for (int k = 0; k < 16; ++k) {
                float ev = __shfl_sync(0xffffffffu, ea, k);
                float2 w = W3s[k][lane];
                c.x += ev * w.x; c.y += ev * w.y;
            }
            acc.x += fmaxf(a.x + b.x + c.x, 0.f);
            acc.y += fmaxf(a.y + b.y + c.y, 0.f);
        }
    }
    ((float2*)agg)[node * 32 + lane] = acc;
}

// ---------------------------------------------------------------------------
// update: x_out = relu([x, agg] @ U + ub), U = 128x64 in smem.
// 8-node register blocking.
// ---------------------------------------------------------------------------
__global__ void update_kernel(const float* __restrict__ x,
                              const float* __restrict__ agg,
                              const float* __restrict__ uw,   // 128x64
                              const float* __restrict__ ub,   // 64
                              float* __restrict__ xout,
                              int n) {
    __shared__ float2 Us[128][32];
    __shared__ float  bs[64];

    int tid = threadIdx.x;
    for (int i = tid; i < 4096; i += 256) {
        int k = i >> 5, c = i & 31;
        Us[k][c] = make_float2(uw[k * 64 + 2 * c], uw[k * 64 + 2 * c + 1]);
    }
    if (tid < 64) bs[tid] = ub[tid];
    __syncthreads();

    int warp = tid >> 5, lane = tid & 31;
    int node0 = blockIdx.x * 64 + warp * 8;
    if (node0 >= n) return;

    float xv0[8], xv1[8], gv0[8], gv1[8];
    float2 acc[8];
#pragma unroll
    for (int i = 0; i < 8; ++i) {
        int nd = node0 + i;
        bool v = nd < n;
        xv0[i] = v ? x[nd * 64 + lane] : 0.f;
        xv1[i] = v ? x[nd * 64 + 32 + lane] : 0.f;
        gv0[i] = v ? agg[nd * 64 + lane] : 0.f;
        gv1[i] = v ? agg[nd * 64 + 32 + lane] : 0.f;
        acc[i] = make_float2(bs[2 * lane], bs[2 * lane + 1]);
    }

#pragma unroll 8
    for (int k = 0; k < 32; ++k) {
        float2 w = Us[k][lane];
#pragma unroll
        for (int i = 0; i < 8; ++i) {
            float vk = __shfl_sync(0xffffffffu, xv0[i], k);
            acc[i].x += vk * w.x; acc[i].y += vk * w.y;
        }
    }
#pragma unroll 8
    for (int k = 0; k < 32; ++k) {
        float2 w = Us[32 + k][lane];
#pragma unroll
        for (int i = 0; i < 8; ++i) {
            float vk = __shfl_sync(0xffffffffu, xv1[i], k);
            acc[i].x += vk * w.x; acc[i].y += vk * w.y;
        }
    }
#pragma unroll 8
    for (int k = 0; k < 32; ++k) {
        float2 w = Us[64 + k][lane];
#pragma unroll
        for (int i = 0; i < 8; ++i) {
            float vk = __shfl_sync(0xffffffffu, gv0[i], k);
            acc[i].x += vk * w.x; acc[i].y += vk * w.y;
        }
    }
#pragma unroll 8
    for (int k = 0; k < 32; ++k) {
        float2 w = Us[96 + k][lane];
#pragma unroll
        for (int i = 0; i < 8; ++i) {
            float vk = __shfl_sync(0xffffffffu, gv1[i], k);
            acc[i].x += vk * w.x; acc[i].y += vk * w.y;
        }
    }

#pragma unroll
    for (int i = 0; i < 8; ++i) {
        int nd = node0 + i;
        if (nd < n) {
            acc[i].x = fmaxf(acc[i].x, 0.f);
            acc[i].y = fmaxf(acc[i].y, 0.f);
            ((float2*)xout)[nd * 32 + lane] = acc[i];
        }
    }
}

extern "C" void kernel_launch(void* const* d_in, const int* in_sizes, int n_in,
                              void* d_out, int out_size) {
    const float* x_in   = (const float*)d_in[0];
    const void*  eidx   = d_in[1];
    const float* eattr  = (const float*)d_in[2];
    const float* msg_w  = (const float*)d_in[3];
    const float* msg_b  = (const float*)d_in[4];
    const float* upd_w  = (const float*)d_in[5];
    const float* upd_b  = (const float*)d_in[6];
    float* out = (float*)d_out;

    int n  = in_sizes[0] / 64;     // nodes
    int ne = in_sizes[2] / 16;     // edges
    if (n > MAX_N)  n  = MAX_N;
    if (ne > MAX_E) ne = MAX_E;

    float *dA, *dB, *dAgg, *dX1, *dX2;
    int *dDeg, *dRow, *dCur, *dSrcA, *dBsums;
    int2 *dEspack;
    cudaGetSymbolAddress((void**)&dA,      g_A);
    cudaGetSymbolAddress((void**)&dB,      g_B);
    cudaGetSymbolAddress((void**)&dAgg,    g_agg);
    cudaGetSymbolAddress((void**)&dX1,     g_x1);
    cudaGetSymbolAddress((void**)&dX2,     g_x2);
    cudaGetSymbolAddress((void**)&dDeg,    g_deg);
    cudaGetSymbolAddress((void**)&dRow,    g_rowptr);
    cudaGetSymbolAddress((void**)&dCur,    g_cursor);
    cudaGetSymbolAddress((void**)&dEspack, g_espack);
    cudaGetSymbolAddress((void**)&dSrcA,   g_srcA);
    cudaGetSymbolAddress((void**)&dBsums,  g_bsums);

    // ---- once per launch: CSR build (edge_index is layer-invariant) ----
    detect_idx_kernel<<<1, 32>>>((const long long*)eidx, 2 * ne);
    zero_deg_kernel<<<(n + 256) / 256, 256>>>(dDeg, n + 1);
    int eb = (ne + 255) / 256;
    if (eb > 3072) eb = 3072;
    extract_hist_kernel<<<eb, 256>>>(eidx, dSrcA, dDeg, ne);

    int nb = (n + SCAN_CHUNK - 1) / SCAN_CHUNK;       // <= 196 for n=50000
    scan_reduce_kernel<<<nb, SCAN_CHUNK>>>(dDeg, dBsums, n);
    scan_bsums_kernel<<<1, 1024>>>(dBsums, dRow, nb, n);
    scan_output_kernel<<<nb, SCAN_CHUNK>>>(dDeg, dBsums, dRow, dCur, n);

    scatter_kernel<<<eb, 256>>>(eidx, dSrcA, dCur, dEspack, ne);

    int node_blocks = (n + 63) / 64;
    int agg_blocks  = (n + 7) / 8;

    const float* x_cur = x_in;
    const int L = 3;
    for (int l = 0; l < L; ++l) {
        const float* mw = msg_w + (size_t)l * 144 * 64;
        const float* mb = msg_b + (size_t)l * 64;
        const float* uw = upd_w + (size_t)l * 128 * 64;
        const float* ub = upd_b + (size_t)l * 64;
        float* x_next = (l == L - 1) ? out : (l == 0 ? dX1 : dX2);

        node_pre_kernel<<<node_blocks, 256>>>(x_cur, mw, mb, dA, dB, n);
        agg_kernel<<<agg_blocks, 256>>>(dA, dB, eattr, dRow, dEspack,
                                        mw + 128 * 64, dAgg, n);
        update_kernel<<<node_blocks, 256>>>(x_cur, dAgg, uw, ub, x_next, n);

        x_cur = x_next;
    }
}

// round 17
// speedup vs baseline: 1.8352x; 1.2265x over previous
#include <cuda_runtime.h>
#include <cuda_bf16.h>

// MPNN backbone, CSR aggregation + register-blocked GEMMs.
// R9 changes (resubmitted; seven infra failures, never executed): agg_kernel holds
// W3 in registers (removes 16 LDS.64/edge ~= 96us/layer of smem-crossbar time),
// value-prefetch in CSR walk, node_pre at launch index 3 (= the one ncu captures).

#define MAX_N 50000
#define MAX_E 800000
#define SCAN_CHUNK 256
#define MAX_BLOCKS ((MAX_N + SCAN_CHUNK - 1) / SCAN_CHUNK + 1)

__device__ float g_A  [MAX_N * 64];
__device__ float g_B  [MAX_N * 64];
__device__ float g_agg[MAX_N * 64];
__device__ float g_x1 [MAX_N * 64];
__device__ float g_x2 [MAX_N * 64];

__device__ int  g_deg   [MAX_N + 1];
__device__ int  g_rowptr[MAX_N + 1];
__device__ int  g_cursor[MAX_N];
__device__ int2 g_espack[MAX_E];     // (src, eid) per CSR slot
__device__ int  g_srcA  [MAX_E];
__device__ int  g_bsums [MAX_BLOCKS];
__device__ int  g_is64;

// ---------------------------------------------------------------------------
__global__ void detect_idx_kernel(const long long* __restrict__ idx, int n_elem) {
    if (threadIdx.x == 0 && blockIdx.x == 0) {
        bool is64 = true;
        int cnt = n_elem < 8 ? n_elem : 8;
        for (int i = 0; i < cnt; ++i) {
            unsigned long long v = (unsigned long long)idx[i];
            if (v >= (unsigned long long)MAX_N) { is64 = false; break; }
        }
        g_is64 = is64 ? 1 : 0;
    }
}

__global__ void zero_deg_kernel(int* __restrict__ deg, int n1) {
    int i = blockIdx.x * blockDim.x + threadIdx.x;
    if (i < n1) deg[i] = 0;
}

__global__ void extract_hist_kernel(const void* __restrict__ eidx,
                                    int* __restrict__ srcA,
                                    int* __restrict__ deg,
                                    int ne) {
    int stride = gridDim.x * blockDim.x;
    const bool is64 = (g_is64 != 0);
    const long long* e64 = (const long long*)eidx;
    const int*       e32 = (const int*)eidx;
    for (int e = blockIdx.x * blockDim.x + threadIdx.x; e < ne; e += stride) {
        int src, dst;
        if (is64) { src = (int)e64[e]; dst = (int)e64[ne + e]; }
        else      { src = e32[e];      dst = e32[ne + e]; }
        srcA[e] = src;
        atomicAdd(&deg[dst], 1);
    }
}

// multi-block exclusive scan
__global__ void scan_reduce_kernel(const int* __restrict__ deg,
                                   int* __restrict__ bsums, int n) {
    __shared__ int sd[SCAN_CHUNK];
    int i = blockIdx.x * SCAN_CHUNK + threadIdx.x;
    int v = (i < n) ? deg[i] : 0;
    sd[threadIdx.x] = v;
    __syncthreads();
    for (int off = SCAN_CHUNK / 2; off > 0; off >>= 1) {
        if (threadIdx.x < off) sd[threadIdx.x] += sd[threadIdx.x + off];
        __syncthreads();
    }
    if (threadIdx.x == 0) bsums[blockIdx.x] = sd[0];
}

__global__ void scan_bsums_kernel(int* __restrict__ bsums,
                                  int* __restrict__ rowptr,
                                  int nb, int n) {
    __shared__ int ss[1024];
    int t = threadIdx.x;
    int v = (t < nb) ? bsums[t] : 0;
    ss[t] = v;
    __syncthreads();
    for (int off = 1; off < 1024; off <<= 1) {
        int u = (t >= off) ? ss[t - off] : 0;
        __syncthreads();
        ss[t] += u;
        __syncthreads();
    }
    if (t < nb) bsums[t] = ss[t] - v;
    if (t == 1023) rowptr[n] = ss[1023];
}

__global__ void scan_output_kernel(const int* __restrict__ deg,
                                   const int* __restrict__ bsums,
                                   int* __restrict__ rowptr,
                                   int* __restrict__ cursor, int n) {
    __shared__ int sd[SCAN_CHUNK];
    int i = blockIdx.x * SCAN_CHUNK + threadIdx.x;
    int v = (i < n) ? deg[i] : 0;
    sd[threadIdx.x] = v;
    __syncthreads();
    for (int off = 1; off < SCAN_CHUNK; off <<= 1) {
        int u = (threadIdx.x >= off) ? sd[threadIdx.x - off] : 0;
        __syncthreads();
        sd[threadIdx.x] += u;
        __syncthreads();
    }
    if (i < n) {
        int excl = bsums[blockIdx.x] + sd[threadIdx.x] - v;
        rowptr[i] = excl;
        cursor[i] = excl;
    }
}

__global__ void scatter_kernel(const void* __restrict__ eidx,
                               const int* __restrict__ srcA,
                               int* __restrict__ cursor,
                               int2* __restrict__ espack,
                               int ne) {
    int stride = gridDim.x * blockDim.x;
    const bool is64 = (g_is64 != 0);
    const long long* e64 = (const long long*)eidx;
    const int*       e32 = (const int*)eidx;
    for (int e = blockIdx.x * blockDim.x + threadIdx.x; e < ne; e += stride) {
        int dst = is64 ? (int)e64[ne + e] : e32[ne + e];
        int slot = atomicAdd(&cursor[dst], 1);
        espack[slot] = make_int2(srcA[e], e);
    }
}

// ---------------------------------------------------------------------------
// node_pre: A = x @ W1 + b, B = x @ W2. 8-node register blocking per warp.
// ---------------------------------------------------------------------------
__global__ void node_pre_kernel(const float* __restrict__ x,
                                const float* __restrict__ mw,   // 144x64
                                const float* __restrict__ mb,   // 64
                                float* __restrict__ A,
                                float* __restrict__ B,
                                int n) {
    __shared__ float2 W1s[64][32];
    __shared__ float2 W2s[64][32];
    __shared__ float  bs[64];

    int tid = threadIdx.x;
    for (int i = tid; i < 2048; i += 256) {
        int k = i >> 5, c = i & 31;
        W1s[k][c] = make_float2(mw[k * 64 + 2 * c], mw[k * 64 + 2 * c + 1]);
        W2s[k][c] = make_float2(mw[(64 + k) * 64 + 2 * c], mw[(64 + k) * 64 + 2 * c + 1]);
    }
    if (tid < 64) bs[tid] = mb[tid];
    __syncthreads();

    int warp = tid >> 5, lane = tid & 31;
    int node0 = blockIdx.x * 64 + warp * 8;
    if (node0 >= n) return;

    float xv0[8], xv1[8];
    float2 accA[8], accB[8];
#pragma unroll
    for (int i = 0; i < 8; ++i) {
        int nd = node0 + i;
        bool v = nd < n;
        xv0[i] = v ? x[nd * 64 + lane] : 0.f;
        xv1[i] = v ? x[nd * 64 + 32 + lane] : 0.f;
        accA[i] = make_float2(bs[2 * lane], bs[2 * lane + 1]);
        accB[i] = make_float2(0.f, 0.f);
    }

#pragma unroll 8
    for (int k = 0; k < 32; ++k) {
        float2 w1 = W1s[k][lane];
        float2 w2 = W2s[k][lane];
#pragma unroll
        for (int i = 0; i < 8; ++i) {
            float xk = __shfl_sync(0xffffffffu, xv0[i], k);
            accA[i].x += xk * w1.x; accA[i].y += xk * w1.y;
            accB[i].x += xk * w2.x; accB[i].y += xk * w2.y;
        }
    }
#pragma unroll 8
    for (int k = 0; k < 32; ++k) {
        float2 w1 = W1s[32 + k][lane];
        float2 w2 = W2s[32 + k][lane];
#pragma unroll
        for (int i = 0; i < 8; ++i) {
            float xk = __shfl_sync(0xffffffffu, xv1[i], k);
            accA[i].x += xk * w1.x; accA[i].y += xk * w1.y;
            accB[i].x += xk * w2.x; accB[i].y += xk * w2.y;
        }
    }

#pragma unroll
    for (int i = 0; i < 8; ++i) {
        int nd = node0 + i;
        if (nd < n) {
            ((float2*)A)[nd * 32 + lane] = accA[i];
            ((float2*)B)[nd * 32 + lane] = accB[i];
        }
    }
}

// ---------------------------------------------------------------------------
// agg: warp per dst node. W3 held in REGISTERS (32/lane) — zero LDS in the
// edge loop. 1-edge value prefetch on espack/B/eattr.
// ---------------------------------------------------------------------------
__global__ void agg_kernel(const float* __restrict__ A,
                           const float* __restrict__ B,
                           const float* __restrict__ eattr,
                           const int* __restrict__ rowptr,
                           const int2* __restrict__ espack,
                           const float* __restrict__ mw3,   // 16x64
                           float* __restrict__ agg,
                           int n) {
    int tid = threadIdx.x;
    int warp = tid >> 5, lane = tid & 31;
    int node = blockIdx.x * 8 + warp;
    if (node >= n) return;

    // W3 column pair for this lane, all 16 k rows -> registers
    float2 w3r[16];
#pragma unroll
    for (int k = 0; k < 16; ++k)
        w3r[k] = ((const float2*)(mw3 + k * 64))[lane];

    float2 a = ((const float2*)A)[node * 32 + lane];
    float2 acc = make_float2(0.f, 0.f);
    int s   = rowptr[node];
    int end = rowptr[node + 1];

    if (s < end) {
        int2 se = espack[s];
        float2 b = ((const float2*)B)[se.x * 32 + lane];
        float ea = (lane < 16) ? eattr[(size_t)se.y * 16 + lane] : 0.f;
        while (s < end) {
            float2 bc = b;
            float eac = ea;
            ++s;
            if (s < end) {                      // prefetch next edge's values
                se = espack[s];
                b  = ((const float2*)B)[se.x * 32 + lane];
                ea = (lane < 16) ? eattr[(size_t)se.y * 16 + lane] : 0.f;
            }
            float2 c = make_float2(0.f, 0.f);
#pragma unroll
            for (int k = 0; k < 16; ++k) {
                float ev = __shfl_sync(0xffffffffu, eac, k);
                c.x += ev * w3r[k].x; c.y += ev * w3r[k].y;
            }
            acc.x += fmaxf(a.x + bc.x + c.x, 0.f);
            acc.y += fmaxf(a.y + bc.y + c.y, 0.f);
        }
    }
    ((float2*)agg)[node * 32 + lane] = acc;
}

// ---------------------------------------------------------------------------
// update: x_out = relu([x, agg] @ U + ub). 8-node register blocking.
// ---------------------------------------------------------------------------
__global__ void update_kernel(const float* __restrict__ x,
                              const float* __restrict__ agg,
                              const float* __restrict__ uw,   // 128x64
                              const float* __restrict__ ub,   // 64
                              float* __restrict__ xout,
                              int n) {
    __shared__ float2 Us[128][32];
    __shared__ float  bs[64];

    int tid = threadIdx.x;
    for (int i = tid; i < 4096; i += 256) {
        int k = i >> 5, c = i & 31;
        Us[k][c] = make_float2(uw[k * 64 + 2 * c], uw[k * 64 + 2 * c + 1]);
    }
    if (tid < 64) bs[tid] = ub[tid];
    __syncthreads();

    int warp = tid >> 5, lane = tid & 31;
    int node0 = blockIdx.x * 64 + warp * 8;
    if (node0 >= n) return;

    float xv0[8], xv1[8], gv0[8], gv1[8];
    float2 acc[8];
#pragma unroll
    for (int i = 0; i < 8; ++i) {
        int nd = node0 + i;
        bool v = nd < n;
        xv0[i] = v ? x[nd * 64 + lane] : 0.f;
        xv1[i] = v ? x[nd * 64 + 32 + lane] : 0.f;
        gv0[i] = v ? agg[nd * 64 + lane] : 0.f;
        gv1[i] = v ? agg[nd * 64 + 32 + lane] : 0.f;
        acc[i] = make_float2(bs[2 * lane], bs[2 * lane + 1]);
    }

#pragma unroll 8
    for (int k = 0; k < 32; ++k) {
        float2 w = Us[k][lane];
#pragma unroll
        for (int i = 0; i < 8; ++i) {
            float vk = __shfl_sync(0xffffffffu, xv0[i], k);
            acc[i].x += vk * w.x; acc[i].y += vk * w.y;
        }
    }
#pragma unroll 8
    for (int k = 0; k < 32; ++k) {
        float2 w = Us[32 + k][lane];
#pragma unroll
        for (int i = 0; i < 8; ++i) {
            float vk = __shfl_sync(0xffffffffu, xv1[i], k);
            acc[i].x += vk * w.x; acc[i].y += vk * w.y;
        }
    }
#pragma unroll 8
    for (int k = 0; k < 32; ++k) {
        float2 w = Us[64 + k][lane];
#pragma unroll
        for (int i = 0; i < 8; ++i) {
            float vk = __shfl_sync(0xffffffffu, gv0[i], k);
            acc[i].x += vk * w.x; acc[i].y += vk * w.y;
        }
    }
#pragma unroll 8
    for (int k = 0; k < 32; ++k) {
        float2 w = Us[96 + k][lane];
#pragma unroll
        for (int i = 0; i < 8; ++i) {
            float vk = __shfl_sync(0xffffffffu, gv1[i], k);
            acc[i].x += vk * w.x; acc[i].y += vk * w.y;
        }
    }

#pragma unroll
    for (int i = 0; i < 8; ++i) {
        int nd = node0 + i;
        if (nd < n) {
            acc[i].x = fmaxf(acc[i].x, 0.f);
            acc[i].y = fmaxf(acc[i].y, 0.f);
            ((float2*)xout)[nd * 32 + lane] = acc[i];
        }
    }
}

extern "C" void kernel_launch(void* const* d_in, const int* in_sizes, int n_in,
                              void* d_out, int out_size) {
    const float* x_in   = (const float*)d_in[0];
    const void*  eidx   = d_in[1];
    const float* eattr  = (const float*)d_in[2];
    const float* msg_w  = (const float*)d_in[3];
    const float* msg_b  = (const float*)d_in[4];
    const float* upd_w  = (const float*)d_in[5];
    const float* upd_b  = (const float*)d_in[6];
    float* out = (float*)d_out;

    int n  = in_sizes[0] / 64;     // nodes
    int ne = in_sizes[2] / 16;     // edges
    if (n > MAX_N)  n  = MAX_N;
    if (ne > MAX_E) ne = MAX_E;

    float *dA, *dB, *dAgg, *dX1, *dX2;
    int *dDeg, *dRow, *dCur, *dSrcA, *dBsums;
    int2 *dEspack;
    cudaGetSymbolAddress((void**)&dA,      g_A);
    cudaGetSymbolAddress((void**)&dB,      g_B);
    cudaGetSymbolAddress((void**)&dAgg,    g_agg);
    cudaGetSymbolAddress((void**)&dX1,     g_x1);
    cudaGetSymbolAddress((void**)&dX2,     g_x2);
    cudaGetSymbolAddress((void**)&dDeg,    g_deg);
    cudaGetSymbolAddress((void**)&dRow,    g_rowptr);
    cudaGetSymbolAddress((void**)&dCur,    g_cursor);
    cudaGetSymbolAddress((void**)&dEspack, g_espack);
    cudaGetSymbolAddress((void**)&dSrcA,   g_srcA);
    cudaGetSymbolAddress((void**)&dBsums,  g_bsums);

    int node_blocks = (n + 63) / 64;
    int agg_blocks  = (n + 7) / 8;
    int eb = (ne + 255) / 256;
    if (eb > 3072) eb = 3072;
    int nb = (n + SCAN_CHUNK - 1) / SCAN_CHUNK;

    // launches 0-2
    detect_idx_kernel<<<1, 32>>>((const long long*)eidx, 2 * ne);
    zero_deg_kernel<<<(n + 256) / 256, 256>>>(dDeg, n + 1);
    extract_hist_kernel<<<eb, 256>>>(eidx, dSrcA, dDeg, ne);

    // launch 3 = the one ncu captures; node_pre layer 0 is CSR-independent
    node_pre_kernel<<<node_blocks, 256>>>(x_in, msg_w, msg_b, dA, dB, n);

    // remaining CSR build
    scan_reduce_kernel<<<nb, SCAN_CHUNK>>>(dDeg, dBsums, n);
    scan_bsums_kernel<<<1, 1024>>>(dBsums, dRow, nb, n);
    scan_output_kernel<<<nb, SCAN_CHUNK>>>(dDeg, dBsums, dRow, dCur, n);
    scatter_kernel<<<eb, 256>>>(eidx, dSrcA, dCur, dEspack, ne);

    const float* x_cur = x_in;
    const int L = 3;
    for (int l = 0; l < L; ++l) {
        const float* mw = msg_w + (size_t)l * 144 * 64;
        const float* mb = msg_b + (size_t)l * 64;
        const float* uw = upd_w + (size_t)l * 128 * 64;
        const float* ub = upd_b + (size_t)l * 64;
        float* x_next = (l == L - 1) ? out : (l == 0 ? dX1 : dX2);

        if (l > 0)   // layer 0's node_pre already launched above
            node_pre_kernel<<<node_blocks, 256>>>(x_cur, mw, mb, dA, dB, n);
        agg_kernel<<<agg_blocks, 256>>>(dA, dB, eattr, dRow, dEspack,
                                        mw + 128 * 64, dAgg, n);
        update_kernel<<<node_blocks, 256>>>(x_cur, dAgg, uw, ub, x_next, n);

        x_cur = x_next;
    }
}